// round 1
// baseline (speedup 1.0000x reference)
#include <cuda_runtime.h>
#include <math.h>

#define B_  4
#define C_  64
#define OC_ 64
#define H_  256
#define W_  256
#define HW_ (H_*W_)            // 65536
#define CHW_ (C_*HW_)          // 4194304
#define TOT_ (B_*CHW_)         // 16777216
#define NPIX_ (B_*HW_)         // 262144
#define MAXOFF_ 64.0f

// Scratch (device globals: no allocation in kernel_launch)
__device__ float  g_dw [TOT_];          // depthwise conv result
__device__ float  g_off[2*TOT_];        // clipped offsets, 128 channels per batch
__device__ float  g_mod[TOT_];          // modulator
__device__ float  g_out[TOT_];          // pre-BN output
__device__ double g_sum  [OC_];
__device__ double g_sumsq[OC_];
__device__ float  g_scale[OC_];
__device__ float  g_shift[OC_];

// ---------------- K1: depthwise 3x3 conv, pad=1 ----------------
__global__ void dw_kernel(const float* __restrict__ x, const float* __restrict__ wdw) {
    __shared__ float sw[C_*9];
    for (int i = threadIdx.x; i < C_*9; i += blockDim.x) sw[i] = wdw[i];
    __syncthreads();
    int idx = blockIdx.x*blockDim.x + threadIdx.x;
    if (idx >= TOT_) return;
    int w = idx & (W_-1);
    int h = (idx >> 8) & (H_-1);
    int c = (idx >> 16) & (C_-1);
    const float* xp = x + (idx - w - (h << 8));   // base of this (b,c) plane
    const float* wp = sw + c*9;
    float acc = 0.f;
#pragma unroll
    for (int ky = 0; ky < 3; ky++) {
        int yy = h + ky - 1;
        if ((unsigned)yy >= H_) continue;
#pragma unroll
        for (int kx = 0; kx < 3; kx++) {
            int xx = w + kx - 1;
            if ((unsigned)xx >= W_) continue;
            acc += __ldg(xp + yy*W_ + xx) * wp[ky*3 + kx];
        }
    }
    g_dw[idx] = acc;
}

// ---------------- K2: pointwise 1x1 conv 64 -> 192, + clip/sigmoid ----------------
__global__ __launch_bounds__(256) void pw_kernel(const float* __restrict__ pww) {
    __shared__ float sw[3*C_*C_];   // 192*64 floats = 48KB
    for (int i = threadIdx.x; i < 3*C_*C_; i += 256) sw[i] = pww[i];
    __syncthreads();
    int p = blockIdx.x*256 + threadIdx.x;      // pixel index
    int b  = p >> 16;
    int hw = p & (HW_-1);
    int base = b*CHW_ + hw;
    float in[C_];
#pragma unroll
    for (int c = 0; c < C_; c++) in[c] = g_dw[base + c*HW_];

#pragma unroll 1
    for (int o = 0; o < 3*C_; o++) {
        const float4* wv = (const float4*)(sw + o*C_);
        float acc = 0.f;
#pragma unroll
        for (int c4 = 0; c4 < C_/4; c4++) {
            float4 wq = wv[c4];
            acc = fmaf(in[4*c4+0], wq.x, acc);
            acc = fmaf(in[4*c4+1], wq.y, acc);
            acc = fmaf(in[4*c4+2], wq.z, acc);
            acc = fmaf(in[4*c4+3], wq.w, acc);
        }
        if (o < 2*C_) {
            // clipped offset, stored as 128-channel tensor per batch
            float v = fminf(fmaxf(acc, -MAXOFF_), MAXOFF_);
            g_off[b*(2*CHW_) + o*HW_ + hw] = v;
        } else {
            g_mod[base + (o - 2*C_)*HW_] = 2.f / (1.f + expf(-acc));
        }
    }
}

// ---------------- K3: bilinear sample * modulator, then 64x64 matmul + bias ----------------
__device__ __forceinline__ float samp(const float* __restrict__ xc, int y, int xx) {
    if ((unsigned)y < H_ && (unsigned)xx < W_) return __ldg(xc + y*W_ + xx);
    return 0.f;
}

__global__ __launch_bounds__(256) void sample_mm_kernel(const float* __restrict__ x,
                                                        const float* __restrict__ wgt,
                                                        const float* __restrict__ bias) {
    __shared__ float sw[OC_*C_];   // 16KB
    __shared__ float sb[OC_];
    for (int i = threadIdx.x; i < OC_*C_; i += 256) sw[i] = wgt[i];
    if (threadIdx.x < OC_) sb[threadIdx.x] = bias[threadIdx.x];
    __syncthreads();

    int p = blockIdx.x*256 + threadIdx.x;
    int b  = p >> 16;
    int hw = p & (HW_-1);
    int h = hw >> 8;
    int w = hw & (W_-1);
    int base = b*CHW_ + hw;
    const float* xb = x + b*CHW_;
    const float* offb = g_off + b*(2*CHW_) + hw;

    float s[C_];
#pragma unroll 1
    for (int c = 0; c < C_; c++) {
        // reference reshape semantics: channel c uses offset channels (2c, 2c+1)
        float oy = offb[(2*c  )*HW_];
        float ox = offb[(2*c+1)*HW_];
        float m  = g_mod[base + c*HW_];
        float yf = (float)h + oy;
        float xf = (float)w + ox;
        float y0 = floorf(yf), x0 = floorf(xf);
        float wy = yf - y0,    wx = xf - x0;
        int y0i = (int)y0, x0i = (int)x0;
        const float* xc = xb + c*HW_;
        float v00 = samp(xc, y0i,   x0i  );
        float v01 = samp(xc, y0i,   x0i+1);
        float v10 = samp(xc, y0i+1, x0i  );
        float v11 = samp(xc, y0i+1, x0i+1);
        float v = (1.f-wy)*((1.f-wx)*v00 + wx*v01) + wy*((1.f-wx)*v10 + wx*v11);
        s[c] = v * m;
    }

#pragma unroll 1
    for (int o = 0; o < OC_; o++) {
        const float4* wv = (const float4*)(sw + o*C_);
        float acc = sb[o];
#pragma unroll
        for (int c4 = 0; c4 < C_/4; c4++) {
            float4 wq = wv[c4];
            acc = fmaf(s[4*c4+0], wq.x, acc);
            acc = fmaf(s[4*c4+1], wq.y, acc);
            acc = fmaf(s[4*c4+2], wq.z, acc);
            acc = fmaf(s[4*c4+3], wq.w, acc);
        }
        g_out[base + o*HW_] = acc;
    }
}

// ---------------- K0: zero stats ----------------
__global__ void zero_stats() {
    if (threadIdx.x < OC_) { g_sum[threadIdx.x] = 0.0; g_sumsq[threadIdx.x] = 0.0; }
}

// ---------------- K4: per-channel sum / sumsq ----------------
__global__ __launch_bounds__(256) void stats_kernel() {
    int b = blockIdx.x >> 6;
    int o = blockIdx.x & (OC_-1);
    const float* pl = g_out + b*CHW_ + o*HW_;
    double s = 0.0, s2 = 0.0;
    for (int i = threadIdx.x; i < HW_; i += 256) {
        double v = (double)pl[i];
        s += v; s2 += v*v;
    }
    __shared__ double sh0[256];
    __shared__ double sh1[256];
    sh0[threadIdx.x] = s; sh1[threadIdx.x] = s2;
    __syncthreads();
    for (int st = 128; st > 0; st >>= 1) {
        if (threadIdx.x < st) {
            sh0[threadIdx.x] += sh0[threadIdx.x+st];
            sh1[threadIdx.x] += sh1[threadIdx.x+st];
        }
        __syncthreads();
    }
    if (threadIdx.x == 0) {
        atomicAdd(&g_sum[o],   sh0[0]);
        atomicAdd(&g_sumsq[o], sh1[0]);
    }
}

// ---------------- K4b: finalize per-channel scale/shift ----------------
__global__ void finalize_stats(const float* __restrict__ gamma, const float* __restrict__ beta) {
    int o = threadIdx.x;
    if (o < OC_) {
        double N = (double)B_ * (double)HW_;
        double mean = g_sum[o] / N;
        double var  = g_sumsq[o] / N - mean*mean;
        double inv  = 1.0 / sqrt(var + 1e-5);
        double gsc  = inv * (double)gamma[o];
        g_scale[o] = (float)gsc;
        g_shift[o] = (float)((double)beta[o] - mean * gsc);
    }
}

// ---------------- K5: BN affine + exact GELU ----------------
__global__ __launch_bounds__(256) void bn_gelu_kernel(float* __restrict__ out) {
    int idx = blockIdx.x*blockDim.x + threadIdx.x;
    if (idx >= TOT_) return;
    int o = (idx >> 16) & (OC_-1);
    float v = g_out[idx] * g_scale[o] + g_shift[o];
    out[idx] = 0.5f * v * (1.f + erff(v * 0.70710678118654752f));
}

extern "C" void kernel_launch(void* const* d_in, const int* in_sizes, int n_in,
                              void* d_out, int out_size) {
    const float* x     = (const float*)d_in[0];
    const float* dww   = (const float*)d_in[1];
    const float* pww   = (const float*)d_in[2];
    const float* wgt   = (const float*)d_in[3];
    const float* bias  = (const float*)d_in[4];
    const float* gamma = (const float*)d_in[5];
    const float* beta  = (const float*)d_in[6];
    float* out = (float*)d_out;

    dw_kernel<<<TOT_/256, 256>>>(x, dww);
    pw_kernel<<<NPIX_/256, 256>>>(pww);
    sample_mm_kernel<<<NPIX_/256, 256>>>(x, wgt, bias);
    zero_stats<<<1, 64>>>();
    stats_kernel<<<B_*OC_, 256>>>();
    finalize_stats<<<1, 64>>>(gamma, beta);
    bn_gelu_kernel<<<TOT_/256, 256>>>(out);
}